// round 3
// baseline (speedup 1.0000x reference)
#include <cuda_runtime.h>
#include <cuda_bf16.h>
#include <math.h>

// ---------------- problem constants ----------------
#define NN      50000
#define EE      800000
#define ETOT    (EE + NN)        // edges + self loops
#define F_IN    512
#define HID     16
#define NH      8
#define HC      (HID * NH)       // 128
#define LBL     40
#define BN_EPS  1e-5f
#define ELU_A   0.2f
#define NSLOPE  0.2f

// ---------------- device scratch (static; no allocation) ----------------
__device__ float g_gbuf[(size_t)NN * HC];   // GEMM output (pre-attention features)
__device__ float g_hbuf[(size_t)NN * HC];   // post-activation features
__device__ float g_as[NN * NH];
__device__ float g_ad[NN * NH];
__device__ float g_as2[NN];
__device__ float g_ad2[NN];
__device__ int   g_counts[NN];
__device__ int   g_cursor[NN];
__device__ int   g_offs[NN];                // exclusive offsets
__device__ int   g_esrc[ETOT];              // CSR: src node per (dst-sorted) edge slot
__device__ int   g_bsum[128];

// ---------------- CSR build ----------------
__global__ void k_zero() {
    int i = blockIdx.x * blockDim.x + threadIdx.x;
    if (i < NN) { g_counts[i] = 0; g_cursor[i] = 0; }
}

__global__ void k_count(const int* __restrict__ ei) {
    int i = blockIdx.x * blockDim.x + threadIdx.x;
    if (i >= ETOT) return;
    int d = (i < EE) ? ei[EE + i] : (i - EE);
    atomicAdd(&g_counts[d], 1);
}

#define SCAN_B 512
#define NBLK   ((NN + SCAN_B - 1) / SCAN_B)   // 98

__global__ void k_scan_part() {
    __shared__ int sh[SCAN_B];
    int b = blockIdx.x, t = threadIdx.x;
    int i = b * SCAN_B + t;
    int v = (i < NN) ? g_counts[i] : 0;
    sh[t] = v; __syncthreads();
    for (int off = 1; off < SCAN_B; off <<= 1) {
        int x = (t >= off) ? sh[t - off] : 0;
        __syncthreads();
        sh[t] += x;
        __syncthreads();
    }
    if (i < NN) g_offs[i] = sh[t];            // inclusive within chunk
    if (t == SCAN_B - 1) g_bsum[b] = sh[t];
}

__global__ void k_scan_sums() {               // 1 block, 128 threads, inclusive scan
    __shared__ int sh[128];
    int t = threadIdx.x;
    sh[t] = (t < NBLK) ? g_bsum[t] : 0; __syncthreads();
    for (int off = 1; off < 128; off <<= 1) {
        int x = (t >= off) ? sh[t - off] : 0;
        __syncthreads();
        sh[t] += x;
        __syncthreads();
    }
    g_bsum[t] = sh[t];
}

__global__ void k_add_back() {
    int i = blockIdx.x * blockDim.x + threadIdx.x;
    if (i >= NN) return;
    int b = i / SCAN_B;
    int base = (b > 0) ? g_bsum[b - 1] : 0;
    g_offs[i] = g_offs[i] - g_counts[i] + base;   // global exclusive
}

__global__ void k_fill(const int* __restrict__ ei) {
    int i = blockIdx.x * blockDim.x + threadIdx.x;
    if (i >= ETOT) return;
    int s, d;
    if (i < EE) { s = ei[i]; d = ei[EE + i]; }
    else        { s = d = i - EE; }
    int slot = g_offs[d] + atomicAdd(&g_cursor[d], 1);
    g_esrc[slot] = s;
}

// ---------------- SGEMM (C = A[M,K] @ B[K,Nc]) ----------------
template<int BM, int BN, int BK, int TM, int TN>
__global__ void sgemm(const float* __restrict__ A, const float* __restrict__ B,
                      float* __restrict__ C, int M, int Nc, int K) {
    constexpr int THREADS = (BM / TM) * (BN / TN);
    __shared__ float As[BK][BM];
    __shared__ float Bs[BK][BN];
    const int tid = threadIdx.x;
    const int tx = tid % (BN / TN);
    const int ty = tid / (BN / TN);
    const int rowBase = blockIdx.y * BM;
    const int colBase = blockIdx.x * BN;

    float acc[TM][TN];
#pragma unroll
    for (int i = 0; i < TM; i++)
#pragma unroll
        for (int j = 0; j < TN; j++) acc[i][j] = 0.f;

    constexpr int A_LD4 = BM * BK / 4;
    constexpr int B_LD4 = BK * BN / 4;

    for (int k0 = 0; k0 < K; k0 += BK) {
#pragma unroll
        for (int it = 0; it < (A_LD4 + THREADS - 1) / THREADS; it++) {
            int i = tid + it * THREADS;
            if (i < A_LD4) {
                int m = i / (BK / 4);
                int kk4 = (i % (BK / 4)) * 4;
                float4 v = make_float4(0.f, 0.f, 0.f, 0.f);
                int gr = rowBase + m;
                if (gr < M) v = *(const float4*)&A[(size_t)gr * K + k0 + kk4];
                As[kk4 + 0][m] = v.x; As[kk4 + 1][m] = v.y;
                As[kk4 + 2][m] = v.z; As[kk4 + 3][m] = v.w;
            }
        }
#pragma unroll
        for (int it = 0; it < (B_LD4 + THREADS - 1) / THREADS; it++) {
            int i = tid + it * THREADS;
            if (i < B_LD4) {
                int kk = i / (BN / 4);
                int c4 = (i % (BN / 4)) * 4;
                int gc = colBase + c4;
                float4 v = make_float4(0.f, 0.f, 0.f, 0.f);
                if (gc + 3 < Nc) {
                    v = *(const float4*)&B[(size_t)(k0 + kk) * Nc + gc];
                } else {
                    float t0 = (gc + 0 < Nc) ? B[(size_t)(k0 + kk) * Nc + gc + 0] : 0.f;
                    float t1 = (gc + 1 < Nc) ? B[(size_t)(k0 + kk) * Nc + gc + 1] : 0.f;
                    float t2 = (gc + 2 < Nc) ? B[(size_t)(k0 + kk) * Nc + gc + 2] : 0.f;
                    float t3 = (gc + 3 < Nc) ? B[(size_t)(k0 + kk) * Nc + gc + 3] : 0.f;
                    v = make_float4(t0, t1, t2, t3);
                }
                *(float4*)&Bs[kk][c4] = v;
            }
        }
        __syncthreads();
#pragma unroll
        for (int kk = 0; kk < BK; kk++) {
            float a[TM], b[TN];
#pragma unroll
            for (int i = 0; i < TM; i++) a[i] = As[kk][ty * TM + i];
#pragma unroll
            for (int j = 0; j < TN; j++) b[j] = Bs[kk][tx * TN + j];
#pragma unroll
            for (int i = 0; i < TM; i++)
#pragma unroll
                for (int j = 0; j < TN; j++)
                    acc[i][j] = fmaf(a[i], b[j], acc[i][j]);
        }
        __syncthreads();
    }
#pragma unroll
    for (int i = 0; i < TM; i++) {
        int gr = rowBase + ty * TM + i;
        if (gr >= M) continue;
#pragma unroll
        for (int j = 0; j < TN; j++) {
            int gc = colBase + tx * TN + j;
            if (gc < Nc) C[(size_t)gr * Nc + gc] = acc[i][j];
        }
    }
}

// ---------------- alpha projections ----------------
// layers 0/1: warp per node; lane l covers channel block lane*4 (head = lane>>2)
__global__ void k_alpha(const float* __restrict__ gbuf,
                        const float* __restrict__ a_src, const float* __restrict__ a_dst,
                        float* __restrict__ as_arr, float* __restrict__ ad_arr) {
    int warp = (blockIdx.x * blockDim.x + threadIdx.x) >> 5;
    if (warp >= NN) return;
    int lane = threadIdx.x & 31;
    float4 hv = *(const float4*)&gbuf[(size_t)warp * HC + lane * 4];
    float4 s4 = *(const float4*)&a_src[lane * 4];
    float4 d4 = *(const float4*)&a_dst[lane * 4];
    float ps = hv.x * s4.x + hv.y * s4.y + hv.z * s4.z + hv.w * s4.w;
    float pd = hv.x * d4.x + hv.y * d4.y + hv.z * d4.z + hv.w * d4.w;
    ps += __shfl_xor_sync(0xffffffffu, ps, 1);
    ps += __shfl_xor_sync(0xffffffffu, ps, 2);
    pd += __shfl_xor_sync(0xffffffffu, pd, 1);
    pd += __shfl_xor_sync(0xffffffffu, pd, 2);
    if ((lane & 3) == 0) {
        as_arr[warp * NH + (lane >> 2)] = ps;
        ad_arr[warp * NH + (lane >> 2)] = pd;
    }
}

// layer 2 (H=1, C=40)
__global__ void k_alpha2(const float* __restrict__ gbuf,
                         const float* __restrict__ a_src, const float* __restrict__ a_dst,
                         float* __restrict__ as_arr, float* __restrict__ ad_arr) {
    int warp = (blockIdx.x * blockDim.x + threadIdx.x) >> 5;
    if (warp >= NN) return;
    int lane = threadIdx.x & 31;
    float v = gbuf[(size_t)warp * LBL + lane];
    float ps = v * a_src[lane];
    float pd = v * a_dst[lane];
    if (lane < 8) {
        float v2 = gbuf[(size_t)warp * LBL + lane + 32];
        ps += v2 * a_src[lane + 32];
        pd += v2 * a_dst[lane + 32];
    }
#pragma unroll
    for (int off = 16; off > 0; off >>= 1) {
        ps += __shfl_xor_sync(0xffffffffu, ps, off);
        pd += __shfl_xor_sync(0xffffffffu, pd, off);
    }
    if (lane == 0) { as_arr[warp] = ps; ad_arr[warp] = pd; }
}

// ---------------- aggregation (pull-style via CSR) ----------------
// layers 0/1: warp per dst node. lane -> (head = lane>>2, 4 channels).
// Fused epilogue: + bias, BatchNorm(eval), ELU(alpha=0.2)
__global__ void k_aggregate(const float* __restrict__ gbuf,
                            const float* __restrict__ as_arr, const float* __restrict__ ad_arr,
                            const float* __restrict__ bias,
                            const float* __restrict__ gam, const float* __restrict__ bet,
                            const float* __restrict__ rm, const float* __restrict__ rv,
                            float* __restrict__ out) {
    int node = (blockIdx.x * blockDim.x + threadIdx.x) >> 5;
    if (node >= NN) return;
    int lane = threadIdx.x & 31;
    int h = lane >> 2;
    float adv = ad_arr[node * NH + h];
    int beg = g_offs[node];
    int end = beg + g_counts[node];

    // pass 1: per-head max of leaky(as[src]+ad[dst])
    float m = -1e30f;
    for (int e = beg; e < end; e++) {
        int s = g_esrc[e];
        float ev = as_arr[s * NH + h] + adv;
        ev = ev > 0.f ? ev : NSLOPE * ev;
        m = fmaxf(m, ev);
    }
    // pass 2: exp-sum + weighted feature accumulate
    float ssum = 0.f;
    float ax = 0.f, ay = 0.f, az = 0.f, aw = 0.f;
    const float4* gb4 = (const float4*)gbuf;
    for (int e = beg; e < end; e++) {
        int s = g_esrc[e];
        float ev = as_arr[s * NH + h] + adv;
        ev = ev > 0.f ? ev : NSLOPE * ev;
        float p = __expf(ev - m);
        ssum += p;
        float4 hv = gb4[(size_t)s * (HC / 4) + lane];
        ax = fmaf(p, hv.x, ax); ay = fmaf(p, hv.y, ay);
        az = fmaf(p, hv.z, az); aw = fmaf(p, hv.w, aw);
    }
    float inv = 1.f / (ssum + 1e-16f);
    int ch = lane * 4;
    float vals[4] = { ax * inv, ay * inv, az * inv, aw * inv };
    float4 o;
    float* op = &o.x;
#pragma unroll
    for (int j = 0; j < 4; j++) {
        float y = vals[j] + bias[ch + j];
        float sc = gam[ch + j] * rsqrtf(rv[ch + j] + BN_EPS);
        y = (y - rm[ch + j]) * sc + bet[ch + j];
        op[j] = y > 0.f ? y : ELU_A * expm1f(y);
    }
    *(float4*)&out[(size_t)node * HC + ch] = o;
}

// layer 2: warp per node, 40 channels (lane and lane+32 for lane<8), single head
__global__ void k_aggregate2(const float* __restrict__ gbuf,
                             const float* __restrict__ as_arr, const float* __restrict__ ad_arr,
                             const float* __restrict__ bias,
                             float* __restrict__ out) {
    int node = (blockIdx.x * blockDim.x + threadIdx.x) >> 5;
    if (node >= NN) return;
    int lane = threadIdx.x & 31;
    float adv = ad_arr[node];
    int beg = g_offs[node];
    int end = beg + g_counts[node];

    float m = -1e30f;
    for (int e = beg; e < end; e++) {
        float ev = as_arr[g_esrc[e]] + adv;
        ev = ev > 0.f ? ev : NSLOPE * ev;
        m = fmaxf(m, ev);
    }
    float ssum = 0.f, a0 = 0.f, a1 = 0.f;
    for (int e = beg; e < end; e++) {
        int s = g_esrc[e];
        float ev = as_arr[s] + adv;
        ev = ev > 0.f ? ev : NSLOPE * ev;
        float p = __expf(ev - m);
        ssum += p;
        a0 = fmaf(p, gbuf[(size_t)s * LBL + lane], a0);
        if (lane < 8) a1 = fmaf(p, gbuf[(size_t)s * LBL + lane + 32], a1);
    }
    float inv = 1.f / (ssum + 1e-16f);
    out[(size_t)node * LBL + lane] = a0 * inv + bias[lane];
    if (lane < 8)
        out[(size_t)node * LBL + lane + 32] = a1 * inv + bias[lane + 32];
}

// ---------------- launch ----------------
extern "C" void kernel_launch(void* const* d_in, const int* in_sizes, int n_in,
                              void* d_out, int out_size) {
    const float* x   = (const float*)d_in[0];
    const int*   ei  = (const int*)d_in[1];
    const float* W0  = (const float*)d_in[2];
    const float* as0 = (const float*)d_in[3];
    const float* ad0 = (const float*)d_in[4];
    const float* b0  = (const float*)d_in[5];
    const float* g0  = (const float*)d_in[6];
    const float* be0 = (const float*)d_in[7];
    const float* rm0 = (const float*)d_in[8];
    const float* rv0 = (const float*)d_in[9];
    const float* W1  = (const float*)d_in[10];
    const float* as1 = (const float*)d_in[11];
    const float* ad1 = (const float*)d_in[12];
    const float* b1  = (const float*)d_in[13];
    const float* g1  = (const float*)d_in[14];
    const float* be1 = (const float*)d_in[15];
    const float* rm1 = (const float*)d_in[16];
    const float* rv1 = (const float*)d_in[17];
    const float* W2  = (const float*)d_in[18];
    const float* as2 = (const float*)d_in[19];
    const float* ad2 = (const float*)d_in[20];
    const float* b2  = (const float*)d_in[21];
    float* out = (float*)d_out;

    float *gbuf, *hbuf, *asb, *adb, *as2b, *ad2b;
    cudaGetSymbolAddress((void**)&gbuf, g_gbuf);
    cudaGetSymbolAddress((void**)&hbuf, g_hbuf);
    cudaGetSymbolAddress((void**)&asb,  g_as);
    cudaGetSymbolAddress((void**)&adb,  g_ad);
    cudaGetSymbolAddress((void**)&as2b, g_as2);
    cudaGetSymbolAddress((void**)&ad2b, g_ad2);

    const int TPB = 256;
    const int nodeBlocks = (NN + TPB - 1) / TPB;          // node-parallel
    const int edgeBlocks = (ETOT + TPB - 1) / TPB;        // edge-parallel
    const int warpBlocks = (NN * 32 + TPB - 1) / TPB;     // warp-per-node

    // CSR build
    k_zero<<<nodeBlocks, TPB>>>();
    k_count<<<edgeBlocks, TPB>>>(ei);
    k_scan_part<<<NBLK, SCAN_B>>>();
    k_scan_sums<<<1, 128>>>();
    k_add_back<<<nodeBlocks, TPB>>>();
    k_fill<<<edgeBlocks, TPB>>>(ei);

    // layer 0
    {
        dim3 grid(1, (NN + 127) / 128);
        sgemm<128, 128, 16, 8, 8><<<grid, 256>>>(x, W0, gbuf, NN, HC, F_IN);
    }
    k_alpha<<<warpBlocks, TPB>>>(gbuf, as0, ad0, asb, adb);
    k_aggregate<<<warpBlocks, TPB>>>(gbuf, asb, adb, b0, g0, be0, rm0, rv0, hbuf);

    // layer 1
    {
        dim3 grid(1, (NN + 127) / 128);
        sgemm<128, 128, 16, 8, 8><<<grid, 256>>>(hbuf, W1, gbuf, NN, HC, HC);
    }
    k_alpha<<<warpBlocks, TPB>>>(gbuf, as1, ad1, asb, adb);
    k_aggregate<<<warpBlocks, TPB>>>(gbuf, asb, adb, b1, g1, be1, rm1, rv1, hbuf);

    // layer 2
    {
        dim3 grid(1, (NN + 63) / 64);
        sgemm<64, 64, 16, 4, 4><<<grid, 256>>>(hbuf, W2, gbuf, NN, LBL, HC);
    }
    k_alpha2<<<warpBlocks, TPB>>>(gbuf, as2, ad2, as2b, ad2b);
    k_aggregate2<<<warpBlocks, TPB>>>(gbuf, as2b, ad2b, b2, out);
}